// round 15
// baseline (speedup 1.0000x reference)
#include <cuda_runtime.h>
#include <math.h>

#define B_ 32
#define S_ 100
#define T_ 64
#define H_ 512
#define E_ 512
#define V_ 32000
#define BE (B_*E_)
#define BH (B_*H_)
#define NBLK 128
#define NTHR 256

// ----------------------------- device scratch ------------------------------
__device__ __align__(256) float g_xe  [T_*B_*E_];   // gathered embeddings [t][b][e]
__device__ __align__(256) float g_outs[T_*B_*E_];   // out_t for all t  (A of logits GEMM)
__device__ __align__(256) float g_h[2][BH];
__device__ __align__(256) float g_ctxp[4*BH];       // partial ctx per s-quad
__device__ __align__(256) float g_t1  [BH];
__device__ __align__(256) float g_Wqb [H_*H_];      // Wb @ Wq
__device__ __align__(256) float g_bqb [H_];         // Wb @ bq + bb
__device__ __align__(256) float g_mem2[B_*100*H_];  // Wqb^T @ m  per (b,s)
__device__ __align__(256) float g_sb  [B_*100];     // bqb . m
__device__ __align__(256) unsigned long long g_flag[NBLK];
__device__ unsigned long long g_rel;
__device__ unsigned long long g_ebase;
__device__ int g_trg64;
__device__ int g_mask4;

// ---------------------- smem layout (floats) --------------------------------
#define OFF_SW   0                        // 16 x 1544 gate rows
#define OFF_SM   24704                    // 25 x 516  src_memory slice
#define OFF_SO1  37604                    // 4 x 1024
#define OFF_SO2  41700                    // 4 x 512
#define OFF_XS   43748                    // 2 x 32 x 68 (aliased as PART[8][512])
#define OFF_SCR  48100                    // 1024
#define OFF_SC   49124                    // 128 cell state
#define SMEM_FLOATS 49252
#define SMEM_BYTES (SMEM_FLOATS*4)

// ------------------------- acquire/release helpers ---------------------------
__device__ __forceinline__ unsigned long long ld_acq(const unsigned long long* p){
    unsigned long long v;
    asm volatile("ld.acquire.gpu.u64 %0, [%1];" : "=l"(v) : "l"(p) : "memory");
    return v;
}
__device__ __forceinline__ void st_rel(unsigned long long* p, unsigned long long v){
    asm volatile("st.release.gpu.u64 [%0], %1;" :: "l"(p), "l"(v) : "memory");
}

// ------------------------- dtype detection ----------------------------------
__global__ void k_detect(const void* trg, const void* mask){
    if (threadIdx.x == 0){
        const int* t32 = (const int*)trg;
        int is64 = 1;
        for (int i = 0; i < 256; i++) if (t32[2*i+1] != 0) { is64 = 0; break; }
        g_trg64 = is64;
        const unsigned char* mb = (const unsigned char*)mask;
        int m4 = 1;
        for (int i = 0; i < 64; i++)
            if (mb[4*i+1] | mb[4*i+2] | mb[4*i+3]) { m4 = 0; break; }
        g_mask4 = m4;
    }
}

// ----------------------------- prologue kernels ------------------------------
__global__ void k_gather(const void* __restrict__ trg, const float* __restrict__ emb){
    int idx = blockIdx.x*256 + threadIdx.x;
    int e   = idx & 511;
    int rem = idx >> 9;
    int b   = rem & 31;
    int t   = rem >> 5;
    long long tok = g_trg64 ? ((const long long*)trg)[b*T_ + t]
                            : (long long)((const int*)trg)[b*T_ + t];
    g_xe[idx] = emb[(size_t)tok*E_ + e];
}

__global__ void k_init(const float* __restrict__ h0){
    int i = blockIdx.x*256 + threadIdx.x;
    g_h[0][i] = h0[i];
}

// fused: blocks [0,64) compute Wqb 64x64 tiles; blocks [64,128) compute bqb.
__global__ __launch_bounds__(256) void k_wqb_bqb(
        const float* __restrict__ Wb, const float* __restrict__ Wq,
        const float* __restrict__ bq, const float* __restrict__ bb){
    __shared__ float Am[64][17];
    __shared__ float Bm[16][68];
    int bx = blockIdx.x;
    if (bx < 64){
        int tx = threadIdx.x & 15, ty = threadIdx.x >> 4;
        int i0 = (bx >> 3)*64, k0 = (bx & 7)*64;
        float acc[4][4] = {};
        for (int m0 = 0; m0 < H_; m0 += 16){
            for (int l = threadIdx.x; l < 1024; l += 256){
                int rr = l >> 4, mm = l & 15;
                Am[rr][mm] = Wb[(size_t)(i0+rr)*H_ + m0 + mm];
            }
            for (int l = threadIdx.x; l < 1024; l += 256){
                int mm = l >> 6, kk = l & 63;
                Bm[mm][kk] = Wq[(size_t)(m0+mm)*H_ + k0 + kk];
            }
            __syncthreads();
#pragma unroll
            for (int mm = 0; mm < 16; mm++){
                float av[4], bv[4];
#pragma unroll
                for (int p = 0; p < 4; p++) av[p] = Am[ty*4+p][mm];
#pragma unroll
                for (int q = 0; q < 4; q++) bv[q] = Bm[mm][tx*4+q];
#pragma unroll
                for (int p = 0; p < 4; p++)
#pragma unroll
                for (int q = 0; q < 4; q++) acc[p][q] += av[p]*bv[q];
            }
            __syncthreads();
        }
#pragma unroll
        for (int p = 0; p < 4; p++)
#pragma unroll
        for (int q = 0; q < 4; q++)
            g_Wqb[(size_t)(i0+ty*4+p)*H_ + k0 + tx*4 + q] = acc[p][q];
    } else {
        int row  = (bx - 64)*8 + (threadIdx.x >> 5);
        int lane = threadIdx.x & 31;
        float s = 0.f;
        for (int m = lane; m < H_; m += 32) s += Wb[(size_t)row*H_ + m]*bq[m];
#pragma unroll
        for (int o = 16; o; o >>= 1) s += __shfl_xor_sync(0xffffffffu, s, o);
        if (lane == 0) g_bqb[row] = s + bb[row];
    }
}

// fused: blocks [0,400) mem2 tiles; blocks [400,800) sb rows.
__global__ __launch_bounds__(256) void k_mem2_sb(const float* __restrict__ mem){
    __shared__ float Am[64][17];
    __shared__ float Bm[16][68];
    int bx = blockIdx.x;
    if (bx < 400){
        int tx = threadIdx.x & 15, ty = threadIdx.x >> 4;
        int r0 = (bx >> 3)*64, k0 = (bx & 7)*64;
        float acc[4][4] = {};
        for (int i0 = 0; i0 < H_; i0 += 16){
            for (int l = threadIdx.x; l < 1024; l += 256){
                int rr = l >> 4, ii = l & 15;
                Am[rr][ii] = mem[(size_t)(r0+rr)*H_ + i0 + ii];
            }
            for (int l = threadIdx.x; l < 1024; l += 256){
                int ii = l >> 6, kk = l & 63;
                Bm[ii][kk] = g_Wqb[(size_t)(i0+ii)*H_ + k0 + kk];
            }
            __syncthreads();
#pragma unroll
            for (int ii = 0; ii < 16; ii++){
                float av[4], bv[4];
#pragma unroll
                for (int p = 0; p < 4; p++) av[p] = Am[ty*4+p][ii];
#pragma unroll
                for (int q = 0; q < 4; q++) bv[q] = Bm[ii][tx*4+q];
#pragma unroll
                for (int p = 0; p < 4; p++)
#pragma unroll
                for (int q = 0; q < 4; q++) acc[p][q] += av[p]*bv[q];
            }
            __syncthreads();
        }
#pragma unroll
        for (int p = 0; p < 4; p++)
#pragma unroll
        for (int q = 0; q < 4; q++)
            g_mem2[(size_t)(r0+ty*4+p)*H_ + k0 + tx*4 + q] = acc[p][q];
    } else {
        int row  = (bx - 400)*8 + (threadIdx.x >> 5);
        int lane = threadIdx.x & 31;
        const float* m = mem + (size_t)row*H_;
        float s = 0.f;
        for (int i = lane; i < H_; i += 32) s += g_bqb[i]*m[i];
#pragma unroll
        for (int o = 16; o; o >>= 1) s += __shfl_xor_sync(0xffffffffu, s, o);
        if (lane == 0) g_sb[row] = s;
    }
}

// --------------------------- grid barrier (flag/release) ---------------------
__device__ __forceinline__ void gbar(int blk, unsigned long long epoch){
    __syncthreads();
    if (blk == 0){
        if (threadIdx.x == 0) st_rel(&g_flag[0], epoch);
        if (threadIdx.x < NBLK){
            while (ld_acq(&g_flag[threadIdx.x]) < epoch) { }
        }
        __syncthreads();
        if (threadIdx.x == 0) st_rel(&g_rel, epoch);
    } else {
        if (threadIdx.x == 0){
            st_rel(&g_flag[blk], epoch);
            while (ld_acq(&g_rel) < epoch) { }
        }
    }
    __syncthreads();
}

// ---------- X staging macros (32 rows x 64 K chunk, double buffered) ---------
#define X_STS(c) { \
    _Pragma("unroll") \
    for (int i_ = 0; i_ < 2; i_++){ \
        int f_ = threadIdx.x*2 + i_; int bl_ = f_ >> 4; int kk4_ = (f_ & 15)*4; \
        *(float4*)(XS + (((c)&1)*32 + bl_)*68 + kk4_) = pre[i_]; } }

// ------------- skinny phase: 4 rows x 32 b, r1 c4 kp8 tiling -----------------
__device__ __forceinline__ void phase_skinny2(
    float* XS, const float* Wsm, int nch,
    const float* X0, const float* X1, int ctx4,
    const float* bias, int row0, float* dst, bool do_tanh)
{
    int tid = threadIdx.x;
    int bgw = tid >> 5, rg = (tid >> 3) & 3, kp = tid & 7;
    int K = nch*64;
    float4 pre[2];
#define SK_LOAD(c) { \
    _Pragma("unroll") \
    for (int i_ = 0; i_ < 2; i_++){ \
        int f_ = tid*2 + i_; int bl_ = f_ >> 4; int kk4_ = (f_ & 15)*4; \
        int kg_ = (c)*64 + kk4_; \
        if (kg_ < 512){ \
            pre[i_] = __ldcg((const float4*)(X0 + bl_*512 + kg_)); \
        } else if (!ctx4){ \
            pre[i_] = __ldcg((const float4*)(X1 + bl_*512 + (kg_-512))); \
        } else { \
            const float4* p_ = (const float4*)(X1 + bl_*512 + (kg_-512)); \
            float4 v0 = __ldcg(p_); \
            float4 v1 = __ldcg(p_ + BH/4); \
            float4 v2 = __ldcg(p_ + 2*(BH/4)); \
            float4 v3 = __ldcg(p_ + 3*(BH/4)); \
            pre[i_] = make_float4(v0.x+v1.x+v2.x+v3.x, v0.y+v1.y+v2.y+v3.y, \
                                  v0.z+v1.z+v2.z+v3.z, v0.w+v1.w+v2.w+v3.w); \
        } } }
    float a0 = 0.f, a1 = 0.f, a2 = 0.f, a3 = 0.f;
    SK_LOAD(0); X_STS(0); __syncthreads();
    for (int c = 0; c < nch; c++){
        if (c+1 < nch) SK_LOAD(c+1);
        const float* xb = XS + ((c&1)*32 + bgw*4)*68 + kp*4;
        const float* wb = Wsm + rg*K + c*64 + kp*4;
#pragma unroll
        for (int j = 0; j < 2; j++){
            float4 w  = *(const float4*)(wb + j*32);
            float4 x0 = *(const float4*)(xb + 0*68 + j*32);
            float4 x1 = *(const float4*)(xb + 1*68 + j*32);
            float4 x2 = *(const float4*)(xb + 2*68 + j*32);
            float4 x3 = *(const float4*)(xb + 3*68 + j*32);
            a0 += w.x*x0.x + w.y*x0.y + w.z*x0.z + w.w*x0.w;
            a1 += w.x*x1.x + w.y*x1.y + w.z*x1.z + w.w*x1.w;
            a2 += w.x*x2.x + w.y*x2.y + w.z*x2.z + w.w*x2.w;
            a3 += w.x*x3.x + w.y*x3.y + w.z*x3.z + w.w*x3.w;
        }
        if (c+1 < nch){ X_STS(c+1); __syncthreads(); }
    }
#pragma unroll
    for (int o = 4; o; o >>= 1){
        a0 += __shfl_down_sync(0xffffffffu, a0, o);
        a1 += __shfl_down_sync(0xffffffffu, a1, o);
        a2 += __shfl_down_sync(0xffffffffu, a2, o);
        a3 += __shfl_down_sync(0xffffffffu, a3, o);
    }
    if (kp == 0){
        float bs = bias[row0 + rg];
        float v0 = a0 + bs, v1 = a1 + bs, v2 = a2 + bs, v3 = a3 + bs;
        if (do_tanh){ v0 = tanhf(v0); v1 = tanhf(v1); v2 = tanhf(v2); v3 = tanhf(v3); }
        dst[(bgw*4+0)*512 + row0 + rg] = v0;
        dst[(bgw*4+1)*512 + row0 + rg] = v1;
        dst[(bgw*4+2)*512 + row0 + rg] = v2;
        dst[(bgw*4+3)*512 + row0 + rg] = v3;
    }
#undef SK_LOAD
    __syncthreads();
}

// -------------------- the persistent 64-step chain kernel -------------------
__global__ __launch_bounds__(NTHR, 1) void k_persist(
    const float* __restrict__ W_ih, const float* __restrict__ W_hh,
    const float* __restrict__ b_ih, const float* __restrict__ b_hh,
    const float* __restrict__ Wo1,  const float* __restrict__ bo1,
    const float* __restrict__ Wo2,  const float* __restrict__ bo2,
    const float* __restrict__ src_memory, const void* __restrict__ mask,
    const float* __restrict__ init_cell,  const float* __restrict__ init_output)
{
    extern __shared__ float smem[];
    float* SW  = smem + OFF_SW;
    float* SM  = smem + OFF_SM;
    float* SO1 = smem + OFF_SO1;
    float* SO2 = smem + OFF_SO2;
    float* XS  = smem + OFF_XS;
    float* SCR = smem + OFF_SCR;
    float* SC  = smem + OFF_SC;

    int tid = threadIdx.x;
    int blk = blockIdx.x;
    int u0  = blk*4;               // unit / row base for row-partitioned phases
    int ab  = blk & 31;            // attn batch
    int sq  = blk >> 5;            // attn s-quad
    int w   = tid >> 5, lane = tid & 31;

    unsigned long long ebase = ld_acq(&g_ebase);
    unsigned long long ep = ebase;

    // ---------------- one-time smem population ----------------
    for (int idx = tid; idx < 6144; idx += NTHR){      // 16 gate rows x 384 float4
        int r = idx / 384, j = idx % 384;
        int grow = (r >> 2)*512 + u0 + (r & 3);
        int kg = j*4;
        float4 v = (kg < 1024) ? *(const float4*)(W_ih + (size_t)grow*1024 + kg)
                               : *(const float4*)(W_hh + (size_t)grow*512 + (kg-1024));
        *(float4*)(SW + r*1544 + kg) = v;
    }
    for (int idx = tid; idx < 3200; idx += NTHR){      // 25 s x 128 float4
        int i = idx >> 7, j = idx & 127;
        float4 v = *(const float4*)(src_memory + ((size_t)ab*S_ + sq*25 + i)*H_ + j*4);
        *(float4*)(SM + i*516 + j*4) = v;
    }
    for (int idx = tid; idx < 1024; idx += NTHR){      // Wo1 4 rows x 256 float4
        int rr = idx >> 8, j = idx & 255;
        *(float4*)(SO1 + rr*1024 + j*4) = *(const float4*)(Wo1 + (size_t)(u0+rr)*1024 + j*4);
    }
    for (int idx = tid; idx < 512; idx += NTHR){       // Wo2 4 rows x 128 float4
        int rr = idx >> 7, j = idx & 127;
        *(float4*)(SO2 + rr*512 + j*4) = *(const float4*)(Wo2 + (size_t)(u0+rr)*512 + j*4);
    }
    if (tid < 128){                                    // cell init [uu*32 + b]
        int uu = tid >> 5, b = tid & 31;
        SC[tid] = init_cell[b*H_ + u0 + uu];
    }
    __syncthreads();

    for (int t = 0; t < T_; t++){
        // ------- phase A: gates GEMM (lane=batch, warp=K-octet) + LSTM cell ------
        {
            const float* xe_t    = g_xe + (size_t)t*BE;
            const float* outprev = t ? g_outs + (size_t)(t-1)*BE : init_output;
            const float* hprev   = g_h[t & 1];
            float4 pre[2];
#define G_LOAD(c) { \
    _Pragma("unroll") \
    for (int i_ = 0; i_ < 2; i_++){ \
        int f_ = tid*2 + i_; int bl_ = f_ >> 4; int kk4_ = (f_ & 15)*4; \
        int kg_ = (c)*64 + kk4_; \
        const float* s_ = (kg_ < 512)  ? xe_t    + bl_*512 + kg_ \
                        : (kg_ < 1024) ? outprev + bl_*512 + (kg_-512) \
                                       : hprev   + bl_*512 + (kg_-1024); \
        pre[i_] = __ldcg((const float4*)s_); } }
            float acc[16];
#pragma unroll
            for (int r = 0; r < 16; r++) acc[r] = 0.f;

            G_LOAD(0); X_STS(0); __syncthreads();
            for (int c = 0; c < 24; c++){
                if (c < 23) G_LOAD(c+1);
                const float* xb = XS + ((c&1)*32 + lane)*68 + w*8;
                float4 x0 = *(const float4*)(xb);
                float4 x1 = *(const float4*)(xb + 4);
                const float* wbp = SW + c*64 + w*8;
#pragma unroll
                for (int r = 0; r < 16; r++){
                    float4 w0 = *(const float4*)(wbp + r*1544);
                    float4 w1 = *(const float4*)(wbp + r*1544 + 4);
                    acc[r] += w0.x*x0.x + w0.y*x0.y + w0.z*x0.z + w0.w*x0.w
                            + w1.x*x1.x + w1.y*x1.y + w1.z*x1.z + w1.w*x1.w;
                }
                if (c < 23){ X_STS(c+1); __syncthreads(); }
            }
            __syncthreads();                 // XS reads done; reuse as PART
            float* PART = XS;
#pragma unroll
            for (int r = 0; r < 16; r++) PART[w*512 + r*32 + lane] = acc[r];
            __syncthreads();
            {
                float s0 = 0.f, s1 = 0.f;
#pragma unroll
                for (int w2 = 0; w2 < 8; w2++){
                    s0 += PART[w2*512 + tid];
                    s1 += PART[w2*512 + 256 + tid];
                }
                SCR[tid] = s0; SCR[256 + tid] = s1;
            }
            __syncthreads();
            if (tid < 128){
                int uu = tid >> 5, b = tid & 31;
                int u  = u0 + uu;
                float iv = SCR[(0*4+uu)*32 + b] + b_ih[u]         + b_hh[u];
                float fv = SCR[(1*4+uu)*32 + b] + b_ih[512 + u]   + b_hh[512 + u];
                float gv = SCR[(2*4+uu)*32 + b] + b_ih[1024 + u]  + b_hh[1024 + u];
                float ov = SCR[(3*4+uu)*32 + b] + b_ih[1536 + u]  + b_hh[1536 + u];
                float is = 1.f/(1.f + expf(-iv));
                float fs = 1.f/(1.f + expf(-fv));
                float os = 1.f/(1.f + expf(-ov));
                float gt = tanhf(gv);
                float cn = fs*SC[tid] + is*gt;
                SC[tid] = cn;
                g_h[(t+1) & 1][b*H_ + u] = os*tanhf(cn);
            }
#undef G_LOAD
        }
        gbar(blk, ++ep);

        // -- phase BC: all 100 scores (redundant) + softmax + partial ctx ----
        {
            if (tid < 128)
                ((float4*)SCR)[tid] = __ldcg(((const float4*)(g_h[(t+1)&1] + ab*H_)) + tid);
            __syncthreads();
            for (int base = 0; base < 112; base += 16){
                int s1 = base + w;
                int s2 = s1 + 8;
                bool v1 = s1 < 100, v2 = s2 < 100;
                const float* m1 = g_mem2 + ((size_t)ab*100 + (v1 ? s1 : 0))*H_;
                const float* m2 = g_mem2 + ((size_t)ab*100 + (v2 ? s2 : 0))*H_;
                float d1 = 0.f, d2 = 0.f;
#pragma unroll
                for (int j = 0; j < 4; j++){
                    int k = lane*4 + j*128;
                    float4 qv = *(const float4*)(SCR + k);
                    float4 av = __ldcg((const float4*)(m1 + k));
                    float4 bv = __ldcg((const float4*)(m2 + k));
                    d1 += qv.x*av.x + qv.y*av.y + qv.z*av.z + qv.w*av.w;
                    d2 += qv.x*bv.x + qv.y*bv.y + qv.z*bv.z + qv.w*bv.w;
                }
#pragma unroll
                for (int o = 16; o; o >>= 1){
                    d1 += __shfl_xor_sync(0xffffffffu, d1, o);
                    d2 += __shfl_xor_sync(0xffffffffu, d2, o);
                }
                if (lane == 0){
                    if (v1){
                        bool mv = g_mask4 ? (((const int*)mask)[ab*S_ + s1] != 0)
                                          : (((const unsigned char*)mask)[ab*S_ + s1] != 0);
                        SCR[512 + s1] = mv ? (d1 + g_sb[ab*100 + s1]) : -1e9f;
                    }
                    if (v2){
                        bool mv = g_mask4 ? (((const int*)mask)[ab*S_ + s2] != 0)
                                          : (((const unsigned char*)mask)[ab*S_ + s2] != 0);
                        SCR[512 + s2] = mv ? (d2 + g_sb[ab*100 + s2]) : -1e9f;
                    }
                }
            }
            __syncthreads();
            if (tid < 32){
                float mx = -1e30f;
#pragma unroll
                for (int j = 0; j < 4; j++){
                    int s = lane + j*32;
                    if (s < 100) mx = fmaxf(mx, SCR[512 + s]);
                }
#pragma unroll
                for (int o = 16; o; o >>= 1) mx = fmaxf(mx, __shfl_xor_sync(0xffffffffu, mx, o));
                float ps = 0.f;
#pragma unroll
                for (int j = 0; j < 4; j++){
                    int s = lane + j*32;
                    if (s < 100) ps += expf(SCR[512 + s] - mx);
                }
#pragma unroll
                for (int o = 16; o; o >>= 1) ps += __shfl_xor_sync(0xffffffffu, ps, o);
                if (lane == 0){ SCR[620] = mx; SCR[621] = 1.f/ps; }
            }
            __syncthreads();
            if (tid < 25)
                SCR[640 + tid] = expf(SCR[512 + sq*25 + tid] - SCR[620]) * SCR[621];
            __syncthreads();
            float c0 = 0.f, c1 = 0.f;
            int h0 = tid, h1 = tid + 256;
            for (int s = 0; s < 25; s++){
                float ws = SCR[640 + s];
                c0 += ws * SM[s*516 + h0];
                c1 += ws * SM[s*516 + h1];
            }
            g_ctxp[sq*BH + ab*H_ + h0] = c0;
            g_ctxp[sq*BH + ab*H_ + h1] = c1;
        }
        gbar(blk, ++ep);

        // ---- phase D: t1 = tanh([h; sum4(ctxp)] @ Wo1^T + bo1) ----
        phase_skinny2(XS, SO1, 16, g_h[(t+1)&1], g_ctxp, 1, bo1, u0, g_t1, true);
        gbar(blk, ++ep);

        // ---- phase E: out = t1 @ Wo2^T + bo2 ----
        phase_skinny2(XS, SO2, 8, g_t1, (const float*)0, 0, bo2, u0,
                      g_outs + (size_t)t*BE, false);
        gbar(blk, ++ep);
    }

    if (blk == 0 && tid == 0) st_rel(&g_ebase, ebase + 1024);
}

// ---------------- tf32 logits GEMM: (2048 x 32000) @ K=512 -----------------
__device__ __forceinline__ unsigned f2t(float f){
    unsigned u;
    asm("cvt.rna.tf32.f32 %0, %1;" : "=r"(u) : "f"(f));
    return u;
}

__global__ __launch_bounds__(256) void k_logits(const float* __restrict__ emb,
                                                float* __restrict__ out){
    __shared__ unsigned As[128][36];
    __shared__ unsigned Bs[128][36];
    int tid = threadIdx.x;
    int m0 = blockIdx.y*128;
    int n0 = blockIdx.x*128;
    int warp = tid >> 5, lane = tid & 31;
    int wm = (warp & 1)*64, wn = (warp >> 1)*32;
    int g = lane >> 2, tg = lane & 3;
    float c[4][4][4];
#pragma unroll
    for (int mt = 0; mt < 4; mt++)
#pragma unroll
    for (int nt = 0; nt < 4; nt++)
#pragma unroll
    for (int r = 0; r < 4; r++) c[mt][nt][r] = 0.f;

    for (int kc = 0; kc < 16; kc++){
        int k0 = kc*32;
#pragma unroll
        for (int i = 0; i < 4; i++){
            int f = tid + i*256;
            int r = f >> 3, k4 = (f & 7)*4;
            float4 va = *(const float4*)(g_outs + (size_t)(m0+r)*512 + k0 + k4);
            As[r][k4]   = f2t(va.x); As[r][k4+1] = f2t(va.y);
            As[r][k4+2] = f2t(va.z); As[r][k4+3] = f2t(va.w);
            float4 vb = *(const float4*)(emb + (size_t)(n0+r)*512 + k0 + k4);
            Bs[r][k4]   = f2t(vb.x); Bs[r][k4+1] = f2t(vb.y);
            Bs[r][k4+2] = f2t(vb.z); Bs[r][k4+3] = f2t(vb.w);
        }
        __syncthreads();
#pragma unroll
        for (int ks = 0; ks < 4; ks++){
            unsigned a[4][4], bf[4][2];
#pragma unroll
            for (int mt = 0; mt < 4; mt++){
                int rr = wm + mt*16 + g;
                a[mt][0] = As[rr  ][ks*8+tg];
                a[mt][1] = As[rr+8][ks*8+tg];
                a[mt][2] = As[rr  ][ks*8+tg+4];
                a[mt][3] = As[rr+8][ks*8+tg+4];
            }
#pragma unroll
            for (int nt = 0; nt < 4; nt++){
                int rr = wn + nt*8 + g;
                bf[nt][0] = Bs[rr][ks*8+tg];
                bf[nt][1] = Bs[rr][ks*8+tg+4];
            }
#pragma unroll
            for (int mt = 0; mt < 4; mt++)
#pragma unroll
            for (int nt = 0; nt < 4; nt++){
                asm volatile(
                    "mma.sync.aligned.m16n8k8.row.col.f32.tf32.tf32.f32 "
                    "{%0,%1,%2,%3}, {%4,%5,%6,%7}, {%8,%9}, {%0,%1,%2,%3};\n"
                    : "+f"(c[mt][nt][0]), "+f"(c[mt][nt][1]),
                      "+f"(c[mt][nt][2]), "+f"(c[mt][nt][3])
                    : "r"(a[mt][0]), "r"(a[mt][1]), "r"(a[mt][2]), "r"(a[mt][3]),
                      "r"(bf[nt][0]), "r"(bf[nt][1]));
            }
        }
        __syncthreads();
    }
#pragma unroll
    for (int mt = 0; mt < 4; mt++){
        int m1 = m0 + wm + mt*16 + g;
        int m2 = m1 + 8;
        int t1 = m1 >> 5, b1 = m1 & 31;
        int t2 = m2 >> 5, b2 = m2 & 31;
#pragma unroll
        for (int nt = 0; nt < 4; nt++){
            int n = n0 + wn + nt*8 + tg*2;
            float2* p1 = (float2*)(out + (size_t)b1*T_*V_ + (size_t)t1*V_ + n);
            *p1 = make_float2(c[mt][nt][0], c[mt][nt][1]);
            float2* p2 = (float2*)(out + (size_t)b2*T_*V_ + (size_t)t2*V_ + n);
            *p2 = make_float2(c[mt][nt][2], c[mt][nt][3]);
        }
    }
}

// ------------------------------- launch ------------------------------------
extern "C" void kernel_launch(void* const* d_in, const int* in_sizes, int n_in,
                              void* d_out, int out_size){
    const float* src_memory  = (const float*)d_in[0];
    const void*  src_mask    = d_in[1];
    const float* init_hidden = (const float*)d_in[2];
    const float* init_cell   = (const float*)d_in[3];
    const float* init_output = (const float*)d_in[4];
    const void*  trg         = d_in[5];
    const float* emb         = (const float*)d_in[6];
    const float* W_ih        = (const float*)d_in[7];
    const float* W_hh        = (const float*)d_in[8];
    const float* b_ih        = (const float*)d_in[9];
    const float* b_hh        = (const float*)d_in[10];
    const float* Wq          = (const float*)d_in[11];
    const float* bq          = (const float*)d_in[12];
    const float* Wb          = (const float*)d_in[13];
    const float* bb          = (const float*)d_in[14];
    const float* Wo1         = (const float*)d_in[15];
    const float* bo1         = (const float*)d_in[16];
    const float* Wo2         = (const float*)d_in[17];
    const float* bo2         = (const float*)d_in[18];
    float* out = (float*)d_out;

    cudaFuncSetAttribute(k_persist,
        cudaFuncAttributeMaxDynamicSharedMemorySize, SMEM_BYTES);

    // 5 launches before k_persist -> ncu (-s 5 -c 1) captures k_persist
    k_detect<<<1, 32>>>(trg, src_mask);                       // 0
    k_gather<<<(T_*B_*E_)/256, 256>>>(trg, emb);              // 1
    k_init<<<BH/256, 256>>>(init_hidden);                     // 2
    k_wqb_bqb<<<128, 256>>>(Wb, Wq, bq, bb);                  // 3
    k_mem2_sb<<<800, 256>>>(src_memory);                      // 4
    k_persist<<<NBLK, NTHR, SMEM_BYTES>>>(                    // 5  <- profiled
        W_ih, W_hh, b_ih, b_hh, Wo1, bo1, Wo2, bo2,
        src_memory, src_mask, init_cell, init_output);
    k_logits<<<dim3(V_/128, (T_*B_)/128), 256>>>(emb, out);   // 6
}